// round 7
// baseline (speedup 1.0000x reference)
#include <cuda_runtime.h>
#include <cuda_bf16.h>
#include <math.h>

#define SEQ 4096
#define DIM 1024

// ---------------------------------------------------------------------------
// Persistent scratch (__device__ globals; no-alloc rule)
// ---------------------------------------------------------------------------
__device__ __nv_bfloat16 g_Xhi[SEQ * DIM];
__device__ __nv_bfloat16 g_Xlo[SEQ * DIM];
__device__ __nv_bfloat16 g_Wthi[3 * DIM * DIM];   // W^T per slot: [n][k]
__device__ __nv_bfloat16 g_Wtlo[3 * DIM * DIM];
__device__ __nv_bfloat16 g_QKVhi[3 * SEQ * DIM];  // Q,K,V row-major [s][d]
__device__ __nv_bfloat16 g_QKVlo[3 * SEQ * DIM];
__device__ __nv_bfloat16 g_Vthi[DIM * SEQ];       // V^T [d][s]
__device__ __nv_bfloat16 g_Vtlo[DIM * SEQ];
__device__ float         g_S[(size_t)SEQ * SEQ];  // scores (unnormalized)
__device__ __nv_bfloat16 g_Phi[(size_t)SEQ * SEQ];
__device__ __nv_bfloat16 g_Plo[(size_t)SEQ * SEQ];
__device__ float         g_rowinv[SEQ];           // 1/rowsum for deferred norm

// ---------------------------------------------------------------------------
// PTX helpers (baseline sm_103: mma.sync / ldmatrix / cp.async)
// ---------------------------------------------------------------------------
__device__ __forceinline__ unsigned smem_u32(const void* p) {
    unsigned a;
    asm("{ .reg .u64 t; cvta.to.shared.u64 t, %1; cvt.u32.u64 %0, t; }"
        : "=r"(a) : "l"(p));
    return a;
}

__device__ __forceinline__ void cp16(unsigned dst, const void* src) {
    asm volatile("cp.async.cg.shared.global [%0], [%1], 16;"
                 :: "r"(dst), "l"(src));
}
#define CP_COMMIT() asm volatile("cp.async.commit_group;" ::: "memory")
#define CP_WAIT1()  asm volatile("cp.async.wait_group 1;" ::: "memory")

__device__ __forceinline__ void ldm_x4(unsigned* r, unsigned addr) {
    asm volatile("ldmatrix.sync.aligned.m8n8.x4.shared.b16 {%0,%1,%2,%3}, [%4];"
                 : "=r"(r[0]), "=r"(r[1]), "=r"(r[2]), "=r"(r[3]) : "r"(addr));
}

__device__ __forceinline__ void mma4(float* c, const unsigned* a, const unsigned* b) {
    asm volatile(
        "mma.sync.aligned.m16n8k16.row.col.f32.bf16.bf16.f32 "
        "{%0,%1,%2,%3}, {%4,%5,%6,%7}, {%8,%9}, {%0,%1,%2,%3};"
        : "+f"(c[0]), "+f"(c[1]), "+f"(c[2]), "+f"(c[3])
        : "r"(a[0]), "r"(a[1]), "r"(a[2]), "r"(a[3]), "r"(b[0]), "r"(b[1]));
}

// ---------------------------------------------------------------------------
// GEMM: C[M,N] = alpha * Asplit @ Bsplit^T (+bias / +row scale)
//   A: (m,k) row-major hi/lo bf16, pitch K
//   B: (n,k) row-major hi/lo bf16, pitch K
// Tile 128x64x32, 8 warps (4m x 2n), warp tile 32x32, 2-stage cp.async.
// __launch_bounds__(256, 3): <=85 regs -> 3 CTAs/SM (24 warps/SM, three
// independent barrier domains for phase staggering).
// ---------------------------------------------------------------------------
#define PITCH       80
#define A_MAT       (128 * PITCH)             // 10240
#define B_MAT       (64 * PITCH)              // 5120
#define STAGE_BYTES (2 * A_MAT + 2 * B_MAT)   // 30720
#define SMEM_BYTES  (2 * STAGE_BYTES)         // 61440
#define OFF_AHI 0
#define OFF_ALO A_MAT
#define OFF_BHI (2 * A_MAT)
#define OFF_BLO (2 * A_MAT + B_MAT)

template <int EPI>
__global__ __launch_bounds__(256, 3) void hmma_gemm(
    const __nv_bfloat16* __restrict__ Ahi, const __nv_bfloat16* __restrict__ Alo,
    const __nv_bfloat16* __restrict__ Bhi, const __nv_bfloat16* __restrict__ Blo,
    const float* __restrict__ bias0, const float* __restrict__ bias1,
    const float* __restrict__ bias2,
    const float* __restrict__ rowScale,
    float* __restrict__ Cf,
    __nv_bfloat16* __restrict__ Chi, __nv_bfloat16* __restrict__ Clo,
    int M, int N, int K, float alpha, size_t bSlot, size_t cSlot)
{
    extern __shared__ char smem[];
    const unsigned sb = smem_u32(smem);
    const int tid = threadIdx.x;
    const int wid = tid >> 5;
    const int lane = tid & 31;
    const int bm = blockIdx.y * 128;
    const int bn = blockIdx.x * 64;
    const int z = blockIdx.z;

    Bhi += (size_t)z * bSlot;
    Blo += (size_t)z * bSlot;

    const int warp_m = wid & 3;   // 0..3 -> 32 rows
    const int warp_n = wid >> 2;  // 0..1 -> 32 cols

    float acc[2][4][4];
    #pragma unroll
    for (int i = 0; i < 2; i++)
        #pragma unroll
        for (int j = 0; j < 4; j++)
            #pragma unroll
            for (int q = 0; q < 4; q++) acc[i][j][q] = 0.0f;

    // ldmatrix per-lane base offsets (bytes within a matrix)
    const unsigned aOff =
        (unsigned)((warp_m * 32 + (lane & 7) + ((lane >> 3) & 1) * 8) * PITCH
                   + (lane >> 4) * 16);
    const unsigned bOff =
        (unsigned)((warp_n * 32 + (lane & 7) + ((lane >> 4) & 1) * 8) * PITCH
                   + ((lane >> 3) & 1) * 16);

    // Loader: 1536 16B-chunks per stage, 6 per thread.
    const int rA = tid >> 2;           // 0..63
    const int c4 = tid & 3;            // 0..3
    const unsigned dOff = (unsigned)(rA * PITCH + c4 * 16);
    const __nv_bfloat16* pa_h = Ahi + (size_t)(bm + rA) * K + c4 * 8;
    const __nv_bfloat16* pa_l = Alo + (size_t)(bm + rA) * K + c4 * 8;
    const __nv_bfloat16* pb_h = Bhi + (size_t)(bn + rA) * K + c4 * 8;
    const __nv_bfloat16* pb_l = Blo + (size_t)(bn + rA) * K + c4 * 8;
    const size_t rstep = (size_t)64 * K;

    auto load_stage = [&](int stg, int kc) {
        const unsigned base = sb + stg * STAGE_BYTES;
        cp16(base + OFF_AHI + dOff,              pa_h + kc);
        cp16(base + OFF_AHI + dOff + 64 * PITCH, pa_h + kc + rstep);
        cp16(base + OFF_ALO + dOff,              pa_l + kc);
        cp16(base + OFF_ALO + dOff + 64 * PITCH, pa_l + kc + rstep);
        cp16(base + OFF_BHI + dOff,              pb_h + kc);
        cp16(base + OFF_BLO + dOff,              pb_l + kc);
    };

    const int nch = K >> 5;
    load_stage(0, 0);
    CP_COMMIT();

    for (int c = 0; c < nch; c++) {
        if (c + 1 < nch) load_stage((c + 1) & 1, (c + 1) << 5);
        CP_COMMIT();
        CP_WAIT1();
        __syncthreads();

        const unsigned stg = sb + (c & 1) * STAGE_BYTES;
        #pragma unroll
        for (int ks = 0; ks < 2; ks++) {
            unsigned ah[2][4], al[2][4];
            #pragma unroll
            for (int im = 0; im < 2; im++) {
                ldm_x4(ah[im], stg + OFF_AHI + aOff + im * (16 * PITCH) + ks * 32);
                ldm_x4(al[im], stg + OFF_ALO + aOff + im * (16 * PITCH) + ks * 32);
            }
            #pragma unroll
            for (int jn = 0; jn < 2; jn++) {
                unsigned bh[4], bl[4];
                ldm_x4(bh, stg + OFF_BHI + bOff + jn * (16 * PITCH) + ks * 32);
                ldm_x4(bl, stg + OFF_BLO + bOff + jn * (16 * PITCH) + ks * 32);
                #pragma unroll
                for (int im = 0; im < 2; im++) {
                    mma4(acc[im][2 * jn],     ah[im], bh + 0);
                    mma4(acc[im][2 * jn],     ah[im], bl + 0);
                    mma4(acc[im][2 * jn],     al[im], bh + 0);
                    mma4(acc[im][2 * jn + 1], ah[im], bh + 2);
                    mma4(acc[im][2 * jn + 1], ah[im], bl + 2);
                    mma4(acc[im][2 * jn + 1], al[im], bh + 2);
                }
            }
        }
        __syncthreads();
    }

    // ---- Epilogue ----
    const int r0 = bm + warp_m * 32 + (lane >> 2);
    const int c0 = bn + warp_n * 32 + (lane & 3) * 2;

    if (EPI == 0) {
        Cf += (size_t)z * cSlot;
        #pragma unroll
        for (int im = 0; im < 2; im++)
            #pragma unroll
            for (int j = 0; j < 4; j++) {
                const int row = r0 + im * 16;
                const int col = c0 + j * 8;
                const float s0 = rowScale ? rowScale[row] : alpha;
                const float s1 = rowScale ? rowScale[row + 8] : alpha;
                float2 v0 = make_float2(s0 * acc[im][j][0], s0 * acc[im][j][1]);
                float2 v1 = make_float2(s1 * acc[im][j][2], s1 * acc[im][j][3]);
                *reinterpret_cast<float2*>(&Cf[(size_t)row * N + col]) = v0;
                *reinterpret_cast<float2*>(&Cf[(size_t)(row + 8) * N + col]) = v1;
            }
    } else {
        const float* bias = (z == 0) ? bias0 : (z == 1) ? bias1 : bias2;
        Chi += (size_t)z * cSlot;
        Clo += (size_t)z * cSlot;
        #pragma unroll
        for (int im = 0; im < 2; im++)
            #pragma unroll
            for (int j = 0; j < 4; j++) {
                const int row = r0 + im * 16;
                const int col = c0 + j * 8;
                const float b0 = bias[col], b1 = bias[col + 1];
                #pragma unroll
                for (int h = 0; h < 2; h++) {
                    const int rr = row + h * 8;
                    float v0 = acc[im][j][h * 2 + 0] + b0;
                    float v1 = acc[im][j][h * 2 + 1] + b1;
                    __nv_bfloat16 h0 = __float2bfloat16(v0);
                    __nv_bfloat16 h1 = __float2bfloat16(v1);
                    __nv_bfloat162 hp; hp.x = h0; hp.y = h1;
                    __nv_bfloat162 lp;
                    lp.x = __float2bfloat16(v0 - __bfloat162float(h0));
                    lp.y = __float2bfloat16(v1 - __bfloat162float(h1));
                    *reinterpret_cast<__nv_bfloat162*>(&Chi[(size_t)rr * N + col]) = hp;
                    *reinterpret_cast<__nv_bfloat162*>(&Clo[(size_t)rr * N + col]) = lp;
                }
            }
    }
}

// ---------------------------------------------------------------------------
// Elementwise split: X fp32 -> hi/lo bf16 (float4 per thread)
// ---------------------------------------------------------------------------
__global__ __launch_bounds__(256) void split_x(
    const float* __restrict__ X, __nv_bfloat16* __restrict__ Hi,
    __nv_bfloat16* __restrict__ Lo)
{
    const size_t i = ((size_t)blockIdx.x * 256 + threadIdx.x) * 4;
    float4 v = *reinterpret_cast<const float4*>(&X[i]);
    __nv_bfloat16 h0 = __float2bfloat16(v.x), h1 = __float2bfloat16(v.y);
    __nv_bfloat16 h2 = __float2bfloat16(v.z), h3 = __float2bfloat16(v.w);
    __nv_bfloat162 hp0, hp1, lp0, lp1;
    hp0.x = h0; hp0.y = h1; hp1.x = h2; hp1.y = h3;
    lp0.x = __float2bfloat16(v.x - __bfloat162float(h0));
    lp0.y = __float2bfloat16(v.y - __bfloat162float(h1));
    lp1.x = __float2bfloat16(v.z - __bfloat162float(h2));
    lp1.y = __float2bfloat16(v.w - __bfloat162float(h3));
    *reinterpret_cast<__nv_bfloat162*>(&Hi[i]) = hp0;
    *reinterpret_cast<__nv_bfloat162*>(&Hi[i + 2]) = hp1;
    *reinterpret_cast<__nv_bfloat162*>(&Lo[i]) = lp0;
    *reinterpret_cast<__nv_bfloat162*>(&Lo[i + 2]) = lp1;
}

// ---------------------------------------------------------------------------
// W [K=1024][N=1024] fp32 -> transposed split W^T hi/lo [n][k], slot z
// ---------------------------------------------------------------------------
__global__ void wsplit(const float* __restrict__ Wq, const float* __restrict__ Wk,
                       const float* __restrict__ Wv,
                       __nv_bfloat16* __restrict__ Thi, __nv_bfloat16* __restrict__ Tlo)
{
    __shared__ float tile[32][33];
    const int z = blockIdx.z;
    const float* W = (z == 0) ? Wq : (z == 1) ? Wk : Wv;
    const int n0 = blockIdx.x * 32, k0 = blockIdx.y * 32;
    const int tx = threadIdx.x, ty = threadIdx.y;
    #pragma unroll
    for (int i = 0; i < 32; i += 8)
        tile[ty + i][tx] = W[(size_t)(k0 + ty + i) * DIM + n0 + tx];
    __syncthreads();
    const size_t base = (size_t)z * DIM * DIM;
    #pragma unroll
    for (int i = 0; i < 32; i += 8) {
        float v = tile[tx][ty + i];   // W[k0+tx][n0+ty+i]
        __nv_bfloat16 h = __float2bfloat16(v);
        const size_t o = base + (size_t)(n0 + ty + i) * DIM + k0 + tx;
        Thi[o] = h;
        Tlo[o] = __float2bfloat16(v - __bfloat162float(h));
    }
}

// ---------------------------------------------------------------------------
// V hi/lo [SEQ][DIM] -> V^T hi/lo [DIM][SEQ]
// ---------------------------------------------------------------------------
__global__ void vtrans(const __nv_bfloat16* __restrict__ Vhi,
                       const __nv_bfloat16* __restrict__ Vlo,
                       __nv_bfloat16* __restrict__ Thi,
                       __nv_bfloat16* __restrict__ Tlo)
{
    __shared__ __nv_bfloat16 th[32][33], tl[32][33];
    const int d0 = blockIdx.x * 32, s0 = blockIdx.y * 32;
    const int tx = threadIdx.x, ty = threadIdx.y;
    #pragma unroll
    for (int i = 0; i < 32; i += 8) {
        th[ty + i][tx] = Vhi[(size_t)(s0 + ty + i) * DIM + d0 + tx];
        tl[ty + i][tx] = Vlo[(size_t)(s0 + ty + i) * DIM + d0 + tx];
    }
    __syncthreads();
    #pragma unroll
    for (int i = 0; i < 32; i += 8) {
        const size_t o = (size_t)(d0 + ty + i) * SEQ + s0 + tx;
        Thi[o] = th[tx][ty + i];
        Tlo[o] = tl[tx][ty + i];
    }
}

// ---------------------------------------------------------------------------
// Row softmax (deferred normalization): P = exp(S - max), split to bf16 hi/lo.
// rowinv[r] = 1/sum applied later in the PV epilogue. 2 passes over S, no
// S writeback. One block per row.
// ---------------------------------------------------------------------------
__global__ __launch_bounds__(256) void softmax_split(
    const float* __restrict__ S, __nv_bfloat16* __restrict__ Phi,
    __nv_bfloat16* __restrict__ Plo, float* __restrict__ rowinv)
{
    const size_t rowoff = (size_t)blockIdx.x * SEQ;
    const float* p = S + rowoff;
    __shared__ float red[256];
    const int tid = threadIdx.x;

    float m = -INFINITY;
    #pragma unroll
    for (int t = 0; t < 4; t++) {
        float4 v = *reinterpret_cast<const float4*>(&p[tid * 4 + t * 1024]);
        m = fmaxf(m, fmaxf(fmaxf(v.x, v.y), fmaxf(v.z, v.w)));
    }
    red[tid] = m;
    __syncthreads();
    for (int s = 128; s > 0; s >>= 1) {
        if (tid < s) red[tid] = fmaxf(red[tid], red[tid + s]);
        __syncthreads();
    }
    m = red[0];
    __syncthreads();

    float sum = 0.0f;
    #pragma unroll
    for (int t = 0; t < 4; t++) {
        const int i = tid * 4 + t * 1024;
        float4 v = *reinterpret_cast<const float4*>(&p[i]);
        v.x = expf(v.x - m); v.y = expf(v.y - m);
        v.z = expf(v.z - m); v.w = expf(v.w - m);
        sum += v.x + v.y + v.z + v.w;
        __nv_bfloat16 h0 = __float2bfloat16(v.x), h1 = __float2bfloat16(v.y);
        __nv_bfloat16 h2 = __float2bfloat16(v.z), h3 = __float2bfloat16(v.w);
        __nv_bfloat162 hp0, hp1, lp0, lp1;
        hp0.x = h0; hp0.y = h1; hp1.x = h2; hp1.y = h3;
        lp0.x = __float2bfloat16(v.x - __bfloat162float(h0));
        lp0.y = __float2bfloat16(v.y - __bfloat162float(h1));
        lp1.x = __float2bfloat16(v.z - __bfloat162float(h2));
        lp1.y = __float2bfloat16(v.w - __bfloat162float(h3));
        *reinterpret_cast<__nv_bfloat162*>(&Phi[rowoff + i]) = hp0;
        *reinterpret_cast<__nv_bfloat162*>(&Phi[rowoff + i + 2]) = hp1;
        *reinterpret_cast<__nv_bfloat162*>(&Plo[rowoff + i]) = lp0;
        *reinterpret_cast<__nv_bfloat162*>(&Plo[rowoff + i + 2]) = lp1;
    }
    red[tid] = sum;
    __syncthreads();
    for (int s = 128; s > 0; s >>= 1) {
        if (tid < s) red[tid] += red[tid + s];
        __syncthreads();
    }
    if (tid == 0) rowinv[blockIdx.x] = 1.0f / red[0];
}

// ---------------------------------------------------------------------------
// Launch — ordered so the ncu capture (launch #4) hits the big QK^T GEMM.
// ---------------------------------------------------------------------------
extern "C" void kernel_launch(void* const* d_in, const int* in_sizes, int n_in,
                              void* d_out, int out_size)
{
    const float* X  = (const float*)d_in[0];
    const float* Wq = (const float*)d_in[1];
    const float* bq = (const float*)d_in[2];
    const float* Wk = (const float*)d_in[3];
    const float* bk = (const float*)d_in[4];
    const float* Wv = (const float*)d_in[5];
    const float* bv = (const float*)d_in[6];
    float* out = (float*)d_out;

    __nv_bfloat16 *Xhi, *Xlo, *Wthi, *Wtlo, *QKVhi, *QKVlo, *Vthi, *Vtlo, *Phi, *Plo;
    float *S, *rowinv;
    cudaGetSymbolAddress((void**)&Xhi, g_Xhi);
    cudaGetSymbolAddress((void**)&Xlo, g_Xlo);
    cudaGetSymbolAddress((void**)&Wthi, g_Wthi);
    cudaGetSymbolAddress((void**)&Wtlo, g_Wtlo);
    cudaGetSymbolAddress((void**)&QKVhi, g_QKVhi);
    cudaGetSymbolAddress((void**)&QKVlo, g_QKVlo);
    cudaGetSymbolAddress((void**)&Vthi, g_Vthi);
    cudaGetSymbolAddress((void**)&Vtlo, g_Vtlo);
    cudaGetSymbolAddress((void**)&S, g_S);
    cudaGetSymbolAddress((void**)&Phi, g_Phi);
    cudaGetSymbolAddress((void**)&Plo, g_Plo);
    cudaGetSymbolAddress((void**)&rowinv, g_rowinv);

    cudaFuncSetAttribute(hmma_gemm<0>, cudaFuncAttributeMaxDynamicSharedMemorySize, SMEM_BYTES);
    cudaFuncSetAttribute(hmma_gemm<1>, cudaFuncAttributeMaxDynamicSharedMemorySize, SMEM_BYTES);

    // 1) split X
    split_x<<<SEQ * DIM / 1024, 256>>>(X, Xhi, Xlo);
    // 2) transpose+split weights into slots
    wsplit<<<dim3(DIM / 32, DIM / 32, 3), dim3(32, 8)>>>(Wq, Wk, Wv, Wthi, Wtlo);
    // 3) QKV projections (fused over z), split epilogue with bias
    hmma_gemm<1><<<dim3(DIM / 64, SEQ / 128, 3), 256, SMEM_BYTES>>>(
        Xhi, Xlo, Wthi, Wtlo, bq, bk, bv, nullptr,
        nullptr, QKVhi, QKVlo,
        SEQ, DIM, DIM, 1.0f, (size_t)DIM * DIM, (size_t)SEQ * DIM);
    // 4) S = (Q @ K^T) / 32   <-- ncu capture target (launch #4)
    hmma_gemm<0><<<dim3(SEQ / 64, SEQ / 128, 1), 256, SMEM_BYTES>>>(
        QKVhi, QKVlo, QKVhi + (size_t)SEQ * DIM, QKVlo + (size_t)SEQ * DIM,
        nullptr, nullptr, nullptr, nullptr, S, nullptr, nullptr,
        SEQ, SEQ, DIM, 1.0f / 32.0f, 0, 0);
    // 5) transpose V hi/lo
    vtrans<<<dim3(DIM / 32, SEQ / 32), dim3(32, 8)>>>(
        QKVhi + 2 * (size_t)SEQ * DIM, QKVlo + 2 * (size_t)SEQ * DIM, Vthi, Vtlo);
    // 6) softmax (deferred norm) + split P
    softmax_split<<<SEQ, 256>>>(S, Phi, Plo, rowinv);
    // 7) out = (P @ V) * rowinv[row]
    hmma_gemm<0><<<dim3(DIM / 64, SEQ / 128, 1), 256, SMEM_BYTES>>>(
        Phi, Plo, Vthi, Vtlo,
        nullptr, nullptr, nullptr, rowinv, out, nullptr, nullptr,
        SEQ, DIM, SEQ, 1.0f, 0, 0);
}

// round 8
// speedup vs baseline: 1.0363x; 1.0363x over previous
#include <cuda_runtime.h>
#include <cuda_bf16.h>
#include <math.h>

#define SEQ 4096
#define DIM 1024

// ---------------------------------------------------------------------------
// Persistent scratch (__device__ globals; no-alloc rule)
// ---------------------------------------------------------------------------
__device__ __nv_bfloat16 g_Xhi[SEQ * DIM];
__device__ __nv_bfloat16 g_Xlo[SEQ * DIM];
__device__ __nv_bfloat16 g_Wthi[3 * DIM * DIM];   // W^T per slot: [n][k]
__device__ __nv_bfloat16 g_Wtlo[3 * DIM * DIM];
__device__ __nv_bfloat16 g_QKVhi[3 * SEQ * DIM];  // Q,K,V row-major [s][d]
__device__ __nv_bfloat16 g_QKVlo[3 * SEQ * DIM];
__device__ __nv_bfloat16 g_Vthi[DIM * SEQ];       // V^T [d][s]
__device__ __nv_bfloat16 g_Vtlo[DIM * SEQ];
__device__ float         g_S[(size_t)SEQ * SEQ];  // scores (unnormalized)
__device__ __nv_bfloat16 g_Phi[(size_t)SEQ * SEQ];
__device__ __nv_bfloat16 g_Plo[(size_t)SEQ * SEQ];
__device__ float         g_rowinv[SEQ];           // 1/rowsum for deferred norm

// ---------------------------------------------------------------------------
// PTX helpers (baseline sm_103: mma.sync / ldmatrix / cp.async)
// ---------------------------------------------------------------------------
__device__ __forceinline__ unsigned smem_u32(const void* p) {
    unsigned a;
    asm("{ .reg .u64 t; cvta.to.shared.u64 t, %1; cvt.u32.u64 %0, t; }"
        : "=r"(a) : "l"(p));
    return a;
}

__device__ __forceinline__ void cp16(unsigned dst, const void* src) {
    asm volatile("cp.async.cg.shared.global [%0], [%1], 16;"
                 :: "r"(dst), "l"(src));
}
#define CP_COMMIT() asm volatile("cp.async.commit_group;" ::: "memory")
#define CP_WAIT1()  asm volatile("cp.async.wait_group 1;" ::: "memory")

__device__ __forceinline__ void ldm_x4(unsigned* r, unsigned addr) {
    asm volatile("ldmatrix.sync.aligned.m8n8.x4.shared.b16 {%0,%1,%2,%3}, [%4];"
                 : "=r"(r[0]), "=r"(r[1]), "=r"(r[2]), "=r"(r[3]) : "r"(addr));
}

__device__ __forceinline__ void mma4(float* c, const unsigned* a, const unsigned* b) {
    asm volatile(
        "mma.sync.aligned.m16n8k16.row.col.f32.bf16.bf16.f32 "
        "{%0,%1,%2,%3}, {%4,%5,%6,%7}, {%8,%9}, {%0,%1,%2,%3};"
        : "+f"(c[0]), "+f"(c[1]), "+f"(c[2]), "+f"(c[3])
        : "r"(a[0]), "r"(a[1]), "r"(a[2]), "r"(a[3]), "r"(b[0]), "r"(b[1]));
}

// ---------------------------------------------------------------------------
// GEMM: C[M,N] = alpha * Asplit @ Bsplit^T (+bias / +row scale)
//   A: (m,k) row-major hi/lo bf16, pitch K
//   B: (n,k) row-major hi/lo bf16, pitch K
// Tile 128x128x32, 8 warps (4m x 2n), warp tile 32x64, 2-stage cp.async.
// Inner loop: term-major MMA order (hh x8, hl x8, lh x8 per jn-pair) so
// dependent MMAs into the same accumulator are 8 issues apart (> HMMA lat).
// ---------------------------------------------------------------------------
#define PITCH      80
#define MAT_BYTES  (128 * PITCH)           // 10240
#define STAGE_BYTES (4 * MAT_BYTES)        // 40960
#define SMEM_BYTES (2 * STAGE_BYTES)       // 81920
#define OFF_AHI 0
#define OFF_ALO MAT_BYTES
#define OFF_BHI (2 * MAT_BYTES)
#define OFF_BLO (3 * MAT_BYTES)

template <int EPI>
__global__ __launch_bounds__(256, 2) void hmma_gemm(
    const __nv_bfloat16* __restrict__ Ahi, const __nv_bfloat16* __restrict__ Alo,
    const __nv_bfloat16* __restrict__ Bhi, const __nv_bfloat16* __restrict__ Blo,
    const float* __restrict__ bias0, const float* __restrict__ bias1,
    const float* __restrict__ bias2,
    const float* __restrict__ rowScale,
    float* __restrict__ Cf,
    __nv_bfloat16* __restrict__ Chi, __nv_bfloat16* __restrict__ Clo,
    int M, int N, int K, float alpha, size_t bSlot, size_t cSlot)
{
    extern __shared__ char smem[];
    const unsigned sb = smem_u32(smem);
    const int tid = threadIdx.x;
    const int wid = tid >> 5;
    const int lane = tid & 31;
    const int bm = blockIdx.y * 128;
    const int bn = blockIdx.x * 128;
    const int z = blockIdx.z;

    Bhi += (size_t)z * bSlot;
    Blo += (size_t)z * bSlot;

    const int warp_m = wid & 3;   // 0..3 -> 32 rows
    const int warp_n = wid >> 2;  // 0..1 -> 64 cols

    float acc[2][8][4];
    #pragma unroll
    for (int i = 0; i < 2; i++)
        #pragma unroll
        for (int j = 0; j < 8; j++)
            #pragma unroll
            for (int q = 0; q < 4; q++) acc[i][j][q] = 0.0f;

    // ldmatrix per-lane base offsets (bytes within a matrix)
    const unsigned aOff =
        (unsigned)((warp_m * 32 + (lane & 7) + ((lane >> 3) & 1) * 8) * PITCH
                   + (lane >> 4) * 16);
    const unsigned bOff =
        (unsigned)((warp_n * 64 + (lane & 7) + ((lane >> 4) & 1) * 8) * PITCH
                   + ((lane >> 3) & 1) * 16);

    // Loader: per thread 8 cp16.
    const int rA = tid >> 2;           // 0..63
    const int c4 = tid & 3;            // 0..3
    const unsigned dOff = (unsigned)(rA * PITCH + c4 * 16);
    const __nv_bfloat16* pa_h = Ahi + (size_t)(bm + rA) * K + c4 * 8;
    const __nv_bfloat16* pa_l = Alo + (size_t)(bm + rA) * K + c4 * 8;
    const __nv_bfloat16* pb_h = Bhi + (size_t)(bn + rA) * K + c4 * 8;
    const __nv_bfloat16* pb_l = Blo + (size_t)(bn + rA) * K + c4 * 8;
    const size_t rstep = (size_t)64 * K;

    auto load_stage = [&](int stg, int kc) {
        const unsigned base = sb + stg * STAGE_BYTES;
        cp16(base + OFF_AHI + dOff,              pa_h + kc);
        cp16(base + OFF_AHI + dOff + 64 * PITCH, pa_h + kc + rstep);
        cp16(base + OFF_ALO + dOff,              pa_l + kc);
        cp16(base + OFF_ALO + dOff + 64 * PITCH, pa_l + kc + rstep);
        cp16(base + OFF_BHI + dOff,              pb_h + kc);
        cp16(base + OFF_BHI + dOff + 64 * PITCH, pb_h + kc + rstep);
        cp16(base + OFF_BLO + dOff,              pb_l + kc);
        cp16(base + OFF_BLO + dOff + 64 * PITCH, pb_l + kc + rstep);
    };

    const int nch = K >> 5;
    load_stage(0, 0);
    CP_COMMIT();

    for (int c = 0; c < nch; c++) {
        if (c + 1 < nch) load_stage((c + 1) & 1, (c + 1) << 5);
        CP_COMMIT();
        CP_WAIT1();
        __syncthreads();

        const unsigned stg = sb + (c & 1) * STAGE_BYTES;
        #pragma unroll
        for (int ks = 0; ks < 2; ks++) {
            unsigned ah[2][4], al[2][4];
            #pragma unroll
            for (int im = 0; im < 2; im++) {
                ldm_x4(ah[im], stg + OFF_AHI + aOff + im * (16 * PITCH) + ks * 32);
                ldm_x4(al[im], stg + OFF_ALO + aOff + im * (16 * PITCH) + ks * 32);
            }
            #pragma unroll
            for (int jp = 0; jp < 2; jp++) {
                // Preload B for a jn-pair: 32 cols = 4 n-tiles (j = 4jp..4jp+3)
                unsigned bh[2][4], bl[2][4];
                ldm_x4(bh[0], stg + OFF_BHI + bOff + (2 * jp) * (16 * PITCH) + ks * 32);
                ldm_x4(bl[0], stg + OFF_BLO + bOff + (2 * jp) * (16 * PITCH) + ks * 32);
                ldm_x4(bh[1], stg + OFF_BHI + bOff + (2 * jp + 1) * (16 * PITCH) + ks * 32);
                ldm_x4(bl[1], stg + OFF_BLO + bOff + (2 * jp + 1) * (16 * PITCH) + ks * 32);
                // Term-major emission: 8 independent MMAs between dependent
                // reuses of any accumulator.
                #pragma unroll
                for (int im = 0; im < 2; im++)
                    #pragma unroll
                    for (int jj = 0; jj < 2; jj++) {
                        const int j0 = 4 * jp + 2 * jj;
                        mma4(acc[im][j0],     ah[im], bh[jj] + 0);  // hh
                        mma4(acc[im][j0 + 1], ah[im], bh[jj] + 2);
                    }
                #pragma unroll
                for (int im = 0; im < 2; im++)
                    #pragma unroll
                    for (int jj = 0; jj < 2; jj++) {
                        const int j0 = 4 * jp + 2 * jj;
                        mma4(acc[im][j0],     ah[im], bl[jj] + 0);  // hl
                        mma4(acc[im][j0 + 1], ah[im], bl[jj] + 2);
                    }
                #pragma unroll
                for (int im = 0; im < 2; im++)
                    #pragma unroll
                    for (int jj = 0; jj < 2; jj++) {
                        const int j0 = 4 * jp + 2 * jj;
                        mma4(acc[im][j0],     al[im], bh[jj] + 0);  // lh
                        mma4(acc[im][j0 + 1], al[im], bh[jj] + 2);
                    }
            }
        }
        __syncthreads();
    }

    // ---- Epilogue ----
    const int r0 = bm + warp_m * 32 + (lane >> 2);
    const int c0 = bn + warp_n * 64 + (lane & 3) * 2;

    if (EPI == 0) {
        Cf += (size_t)z * cSlot;
        #pragma unroll
        for (int im = 0; im < 2; im++)
            #pragma unroll
            for (int j = 0; j < 8; j++) {
                const int row = r0 + im * 16;
                const int col = c0 + j * 8;
                const float s0 = rowScale ? rowScale[row] : alpha;
                const float s1 = rowScale ? rowScale[row + 8] : alpha;
                float2 v0 = make_float2(s0 * acc[im][j][0], s0 * acc[im][j][1]);
                float2 v1 = make_float2(s1 * acc[im][j][2], s1 * acc[im][j][3]);
                *reinterpret_cast<float2*>(&Cf[(size_t)row * N + col]) = v0;
                *reinterpret_cast<float2*>(&Cf[(size_t)(row + 8) * N + col]) = v1;
            }
    } else {
        const float* bias = (z == 0) ? bias0 : (z == 1) ? bias1 : bias2;
        Chi += (size_t)z * cSlot;
        Clo += (size_t)z * cSlot;
        #pragma unroll
        for (int im = 0; im < 2; im++)
            #pragma unroll
            for (int j = 0; j < 8; j++) {
                const int row = r0 + im * 16;
                const int col = c0 + j * 8;
                const float b0 = bias[col], b1 = bias[col + 1];
                #pragma unroll
                for (int h = 0; h < 2; h++) {
                    const int rr = row + h * 8;
                    float v0 = acc[im][j][h * 2 + 0] + b0;
                    float v1 = acc[im][j][h * 2 + 1] + b1;
                    __nv_bfloat16 h0 = __float2bfloat16(v0);
                    __nv_bfloat16 h1 = __float2bfloat16(v1);
                    __nv_bfloat162 hp; hp.x = h0; hp.y = h1;
                    __nv_bfloat162 lp;
                    lp.x = __float2bfloat16(v0 - __bfloat162float(h0));
                    lp.y = __float2bfloat16(v1 - __bfloat162float(h1));
                    *reinterpret_cast<__nv_bfloat162*>(&Chi[(size_t)rr * N + col]) = hp;
                    *reinterpret_cast<__nv_bfloat162*>(&Clo[(size_t)rr * N + col]) = lp;
                }
            }
    }
}

// ---------------------------------------------------------------------------
// Elementwise split: X fp32 -> hi/lo bf16 (float4 per thread)
// ---------------------------------------------------------------------------
__global__ __launch_bounds__(256) void split_x(
    const float* __restrict__ X, __nv_bfloat16* __restrict__ Hi,
    __nv_bfloat16* __restrict__ Lo)
{
    const size_t i = ((size_t)blockIdx.x * 256 + threadIdx.x) * 4;
    float4 v = *reinterpret_cast<const float4*>(&X[i]);
    __nv_bfloat16 h0 = __float2bfloat16(v.x), h1 = __float2bfloat16(v.y);
    __nv_bfloat16 h2 = __float2bfloat16(v.z), h3 = __float2bfloat16(v.w);
    __nv_bfloat162 hp0, hp1, lp0, lp1;
    hp0.x = h0; hp0.y = h1; hp1.x = h2; hp1.y = h3;
    lp0.x = __float2bfloat16(v.x - __bfloat162float(h0));
    lp0.y = __float2bfloat16(v.y - __bfloat162float(h1));
    lp1.x = __float2bfloat16(v.z - __bfloat162float(h2));
    lp1.y = __float2bfloat16(v.w - __bfloat162float(h3));
    *reinterpret_cast<__nv_bfloat162*>(&Hi[i]) = hp0;
    *reinterpret_cast<__nv_bfloat162*>(&Hi[i + 2]) = hp1;
    *reinterpret_cast<__nv_bfloat162*>(&Lo[i]) = lp0;
    *reinterpret_cast<__nv_bfloat162*>(&Lo[i + 2]) = lp1;
}

// ---------------------------------------------------------------------------
// W [K=1024][N=1024] fp32 -> transposed split W^T hi/lo [n][k], slot z
// ---------------------------------------------------------------------------
__global__ void wsplit(const float* __restrict__ Wq, const float* __restrict__ Wk,
                       const float* __restrict__ Wv,
                       __nv_bfloat16* __restrict__ Thi, __nv_bfloat16* __restrict__ Tlo)
{
    __shared__ float tile[32][33];
    const int z = blockIdx.z;
    const float* W = (z == 0) ? Wq : (z == 1) ? Wk : Wv;
    const int n0 = blockIdx.x * 32, k0 = blockIdx.y * 32;
    const int tx = threadIdx.x, ty = threadIdx.y;
    #pragma unroll
    for (int i = 0; i < 32; i += 8)
        tile[ty + i][tx] = W[(size_t)(k0 + ty + i) * DIM + n0 + tx];
    __syncthreads();
    const size_t base = (size_t)z * DIM * DIM;
    #pragma unroll
    for (int i = 0; i < 32; i += 8) {
        float v = tile[tx][ty + i];   // W[k0+tx][n0+ty+i]
        __nv_bfloat16 h = __float2bfloat16(v);
        const size_t o = base + (size_t)(n0 + ty + i) * DIM + k0 + tx;
        Thi[o] = h;
        Tlo[o] = __float2bfloat16(v - __bfloat162float(h));
    }
}

// ---------------------------------------------------------------------------
// V hi/lo [SEQ][DIM] -> V^T hi/lo [DIM][SEQ]
// ---------------------------------------------------------------------------
__global__ void vtrans(const __nv_bfloat16* __restrict__ Vhi,
                       const __nv_bfloat16* __restrict__ Vlo,
                       __nv_bfloat16* __restrict__ Thi,
                       __nv_bfloat16* __restrict__ Tlo)
{
    __shared__ __nv_bfloat16 th[32][33], tl[32][33];
    const int d0 = blockIdx.x * 32, s0 = blockIdx.y * 32;
    const int tx = threadIdx.x, ty = threadIdx.y;
    #pragma unroll
    for (int i = 0; i < 32; i += 8) {
        th[ty + i][tx] = Vhi[(size_t)(s0 + ty + i) * DIM + d0 + tx];
        tl[ty + i][tx] = Vlo[(size_t)(s0 + ty + i) * DIM + d0 + tx];
    }
    __syncthreads();
    #pragma unroll
    for (int i = 0; i < 32; i += 8) {
        const size_t o = (size_t)(d0 + ty + i) * SEQ + s0 + tx;
        Thi[o] = th[tx][ty + i];
        Tlo[o] = tl[tx][ty + i];
    }
}

// ---------------------------------------------------------------------------
// Row softmax (deferred normalization): P = exp(S - max), split to bf16 hi/lo.
// rowinv[r] = 1/sum applied later in the PV epilogue. One block per row.
// ---------------------------------------------------------------------------
__global__ __launch_bounds__(256) void softmax_split(
    const float* __restrict__ S, __nv_bfloat16* __restrict__ Phi,
    __nv_bfloat16* __restrict__ Plo, float* __restrict__ rowinv)
{
    const size_t rowoff = (size_t)blockIdx.x * SEQ;
    const float* p = S + rowoff;
    __shared__ float red[256];
    const int tid = threadIdx.x;

    float m = -INFINITY;
    #pragma unroll
    for (int t = 0; t < 4; t++) {
        float4 v = *reinterpret_cast<const float4*>(&p[tid * 4 + t * 1024]);
        m = fmaxf(m, fmaxf(fmaxf(v.x, v.y), fmaxf(v.z, v.w)));
    }
    red[tid] = m;
    __syncthreads();
    for (int s = 128; s > 0; s >>= 1) {
        if (tid < s) red[tid] = fmaxf(red[tid], red[tid + s]);
        __syncthreads();
    }
    m = red[0];
    __syncthreads();

    float sum = 0.0f;
    #pragma unroll
    for (int t = 0; t < 4; t++) {
        const int i = tid * 4 + t * 1024;
        float4 v = *reinterpret_cast<const float4*>(&p[i]);
        v.x = expf(v.x - m); v.y = expf(v.y - m);
        v.z = expf(v.z - m); v.w = expf(v.w - m);
        sum += v.x + v.y + v.z + v.w;
        __nv_bfloat16 h0 = __float2bfloat16(v.x), h1 = __float2bfloat16(v.y);
        __nv_bfloat16 h2 = __float2bfloat16(v.z), h3 = __float2bfloat16(v.w);
        __nv_bfloat162 hp0, hp1, lp0, lp1;
        hp0.x = h0; hp0.y = h1; hp1.x = h2; hp1.y = h3;
        lp0.x = __float2bfloat16(v.x - __bfloat162float(h0));
        lp0.y = __float2bfloat16(v.y - __bfloat162float(h1));
        lp1.x = __float2bfloat16(v.z - __bfloat162float(h2));
        lp1.y = __float2bfloat16(v.w - __bfloat162float(h3));
        *reinterpret_cast<__nv_bfloat162*>(&Phi[rowoff + i]) = hp0;
        *reinterpret_cast<__nv_bfloat162*>(&Phi[rowoff + i + 2]) = hp1;
        *reinterpret_cast<__nv_bfloat162*>(&Plo[rowoff + i]) = lp0;
        *reinterpret_cast<__nv_bfloat162*>(&Plo[rowoff + i + 2]) = lp1;
    }
    red[tid] = sum;
    __syncthreads();
    for (int s = 128; s > 0; s >>= 1) {
        if (tid < s) red[tid] += red[tid + s];
        __syncthreads();
    }
    if (tid == 0) rowinv[blockIdx.x] = 1.0f / red[0];
}

// ---------------------------------------------------------------------------
// Launch — ordered so the ncu capture (launch #4) hits the big QK^T GEMM.
// ---------------------------------------------------------------------------
extern "C" void kernel_launch(void* const* d_in, const int* in_sizes, int n_in,
                              void* d_out, int out_size)
{
    const float* X  = (const float*)d_in[0];
    const float* Wq = (const float*)d_in[1];
    const float* bq = (const float*)d_in[2];
    const float* Wk = (const float*)d_in[3];
    const float* bk = (const float*)d_in[4];
    const float* Wv = (const float*)d_in[5];
    const float* bv = (const float*)d_in[6];
    float* out = (float*)d_out;

    __nv_bfloat16 *Xhi, *Xlo, *Wthi, *Wtlo, *QKVhi, *QKVlo, *Vthi, *Vtlo, *Phi, *Plo;
    float *S, *rowinv;
    cudaGetSymbolAddress((void**)&Xhi, g_Xhi);
    cudaGetSymbolAddress((void**)&Xlo, g_Xlo);
    cudaGetSymbolAddress((void**)&Wthi, g_Wthi);
    cudaGetSymbolAddress((void**)&Wtlo, g_Wtlo);
    cudaGetSymbolAddress((void**)&QKVhi, g_QKVhi);
    cudaGetSymbolAddress((void**)&QKVlo, g_QKVlo);
    cudaGetSymbolAddress((void**)&Vthi, g_Vthi);
    cudaGetSymbolAddress((void**)&Vtlo, g_Vtlo);
    cudaGetSymbolAddress((void**)&S, g_S);
    cudaGetSymbolAddress((void**)&Phi, g_Phi);
    cudaGetSymbolAddress((void**)&Plo, g_Plo);
    cudaGetSymbolAddress((void**)&rowinv, g_rowinv);

    cudaFuncSetAttribute(hmma_gemm<0>, cudaFuncAttributeMaxDynamicSharedMemorySize, SMEM_BYTES);
    cudaFuncSetAttribute(hmma_gemm<1>, cudaFuncAttributeMaxDynamicSharedMemorySize, SMEM_BYTES);

    // 1) split X
    split_x<<<SEQ * DIM / 1024, 256>>>(X, Xhi, Xlo);
    // 2) transpose+split weights into slots
    wsplit<<<dim3(DIM / 32, DIM / 32, 3), dim3(32, 8)>>>(Wq, Wk, Wv, Wthi, Wtlo);
    // 3) QKV projections (fused over z), split epilogue with bias
    hmma_gemm<1><<<dim3(DIM / 128, SEQ / 128, 3), 256, SMEM_BYTES>>>(
        Xhi, Xlo, Wthi, Wtlo, bq, bk, bv, nullptr,
        nullptr, QKVhi, QKVlo,
        SEQ, DIM, DIM, 1.0f, (size_t)DIM * DIM, (size_t)SEQ * DIM);
    // 4) S = (Q @ K^T) / 32   <-- ncu capture target (launch #4)
    hmma_gemm<0><<<dim3(SEQ / 128, SEQ / 128, 1), 256, SMEM_BYTES>>>(
        QKVhi, QKVlo, QKVhi + (size_t)SEQ * DIM, QKVlo + (size_t)SEQ * DIM,
        nullptr, nullptr, nullptr, nullptr, S, nullptr, nullptr,
        SEQ, SEQ, DIM, 1.0f / 32.0f, 0, 0);
    // 5) transpose V hi/lo
    vtrans<<<dim3(DIM / 32, SEQ / 32), dim3(32, 8)>>>(
        QKVhi + 2 * (size_t)SEQ * DIM, QKVlo + 2 * (size_t)SEQ * DIM, Vthi, Vtlo);
    // 6) softmax (deferred norm) + split P
    softmax_split<<<SEQ, 256>>>(S, Phi, Plo, rowinv);
    // 7) out = (P @ V) * rowinv[row]
    hmma_gemm<0><<<dim3(DIM / 128, SEQ / 128, 1), 256, SMEM_BYTES>>>(
        Phi, Plo, Vthi, Vtlo,
        nullptr, nullptr, nullptr, rowinv, out, nullptr, nullptr,
        SEQ, DIM, SEQ, 1.0f, 0, 0);
}

// round 9
// speedup vs baseline: 1.9211x; 1.8539x over previous
#include <cuda_runtime.h>
#include <cuda_fp16.h>
#include <math.h>

#define SEQ 4096
#define DIM 1024

// ---------------------------------------------------------------------------
// Persistent scratch (__device__ globals; no-alloc rule)
// ---------------------------------------------------------------------------
__device__ __half g_Xh[SEQ * DIM];            // X cast to fp16
__device__ __half g_Wth[3 * DIM * DIM];       // W^T per slot: [n][k] fp16
__device__ __half g_QKVh[3 * SEQ * DIM];      // Q,K,V row-major [s][d] fp16
__device__ __half g_Vth[DIM * SEQ];           // V^T [d][s] fp16
__device__ float  g_S[(size_t)SEQ * SEQ];     // scores (unnormalized)
__device__ __half g_Ph[(size_t)SEQ * SEQ];    // exp(S - max) fp16
__device__ float  g_rowinv[SEQ];              // 1/rowsum for deferred norm

// ---------------------------------------------------------------------------
// PTX helpers
// ---------------------------------------------------------------------------
__device__ __forceinline__ unsigned smem_u32(const void* p) {
    unsigned a;
    asm("{ .reg .u64 t; cvta.to.shared.u64 t, %1; cvt.u32.u64 %0, t; }"
        : "=r"(a) : "l"(p));
    return a;
}

__device__ __forceinline__ void cp16(unsigned dst, const void* src) {
    asm volatile("cp.async.cg.shared.global [%0], [%1], 16;"
                 :: "r"(dst), "l"(src));
}
#define CP_COMMIT() asm volatile("cp.async.commit_group;" ::: "memory")
#define CP_WAIT1()  asm volatile("cp.async.wait_group 1;" ::: "memory")

__device__ __forceinline__ void ldm_x4(unsigned* r, unsigned addr) {
    asm volatile("ldmatrix.sync.aligned.m8n8.x4.shared.b16 {%0,%1,%2,%3}, [%4];"
                 : "=r"(r[0]), "=r"(r[1]), "=r"(r[2]), "=r"(r[3]) : "r"(addr));
}

__device__ __forceinline__ void mma4h(float* c, const unsigned* a, const unsigned* b) {
    asm volatile(
        "mma.sync.aligned.m16n8k16.row.col.f32.f16.f16.f32 "
        "{%0,%1,%2,%3}, {%4,%5,%6,%7}, {%8,%9}, {%0,%1,%2,%3};"
        : "+f"(c[0]), "+f"(c[1]), "+f"(c[2]), "+f"(c[3])
        : "r"(a[0]), "r"(a[1]), "r"(a[2]), "r"(a[3]), "r"(b[0]), "r"(b[1]));
}

// ---------------------------------------------------------------------------
// fp16 GEMM: C[M,N] = scale * A @ B^T (+bias)
//   A: (m,k) row-major fp16, pitch K;  B: (n,k) row-major fp16, pitch K
//   EPI=0: Cf fp32 = (rowScale[row] or alpha) * acc
//   EPI=1: Ch fp16 = acc + bias[col]
// Tile 128x128xBK64, 8 warps (4m x 2n), warp tile 32x64, 2-stage cp.async.
// PITCH=144B: 144 mod 128 = 16 -> conflict-free ldmatrix over 8-row groups.
// ---------------------------------------------------------------------------
#define PITCH       144
#define MAT_BYTES   (128 * PITCH)            // 18432
#define STAGE_BYTES (2 * MAT_BYTES)          // 36864
#define SMEM_BYTES  (2 * STAGE_BYTES)        // 73728
#define OFF_A 0
#define OFF_B MAT_BYTES

template <int EPI>
__global__ __launch_bounds__(256, 2) void h16_gemm(
    const __half* __restrict__ A, const __half* __restrict__ B,
    const float* __restrict__ bias0, const float* __restrict__ bias1,
    const float* __restrict__ bias2,
    const float* __restrict__ rowScale,
    float* __restrict__ Cf, __half* __restrict__ Ch,
    int M, int N, int K, float alpha, size_t bSlot, size_t cSlot)
{
    extern __shared__ char smem[];
    const unsigned sb = smem_u32(smem);
    const int tid = threadIdx.x;
    const int wid = tid >> 5;
    const int lane = tid & 31;
    const int bm = blockIdx.y * 128;
    const int bn = blockIdx.x * 128;
    const int z = blockIdx.z;

    B += (size_t)z * bSlot;

    const int warp_m = wid & 3;   // 0..3 -> 32 rows
    const int warp_n = wid >> 2;  // 0..1 -> 64 cols

    float acc[2][8][4];
    #pragma unroll
    for (int i = 0; i < 2; i++)
        #pragma unroll
        for (int j = 0; j < 8; j++)
            #pragma unroll
            for (int q = 0; q < 4; q++) acc[i][j][q] = 0.0f;

    // ldmatrix per-lane base offsets
    const unsigned aOff =
        (unsigned)((warp_m * 32 + (lane & 7) + ((lane >> 3) & 1) * 8) * PITCH
                   + (lane >> 4) * 16);
    const unsigned bOff =
        (unsigned)((warp_n * 64 + (lane & 7) + ((lane >> 4) & 1) * 8) * PITCH
                   + ((lane >> 3) & 1) * 16);

    // Loader: row = tid>>1 (0..127), 4+4 16B chunks (64 fp16 = 128B per row).
    const int rr = tid >> 1;
    const int ch0 = (tid & 1) * 4;            // chunk 0 or 4
    const unsigned dOff = (unsigned)(rr * PITCH + ch0 * 16);
    const __half* pa = A + (size_t)(bm + rr) * K + ch0 * 8;
    const __half* pb = B + (size_t)(bn + rr) * K + ch0 * 8;

    auto load_stage = [&](int stg, int kc) {
        const unsigned base = sb + stg * STAGE_BYTES;
        #pragma unroll
        for (int j = 0; j < 4; j++)
            cp16(base + OFF_A + dOff + j * 16, pa + kc + j * 8);
        #pragma unroll
        for (int j = 0; j < 4; j++)
            cp16(base + OFF_B + dOff + j * 16, pb + kc + j * 8);
    };

    const int nch = K >> 6;                   // BK = 64
    load_stage(0, 0);
    CP_COMMIT();

    for (int c = 0; c < nch; c++) {
        if (c + 1 < nch) load_stage((c + 1) & 1, (c + 1) << 6);
        CP_COMMIT();
        CP_WAIT1();
        __syncthreads();

        const unsigned stg = sb + (c & 1) * STAGE_BYTES;
        #pragma unroll
        for (int ks = 0; ks < 4; ks++) {
            unsigned ah[2][4];
            #pragma unroll
            for (int im = 0; im < 2; im++)
                ldm_x4(ah[im], stg + OFF_A + aOff + im * (16 * PITCH) + ks * 32);
            unsigned bb[4][4];
            #pragma unroll
            for (int jn = 0; jn < 4; jn++)
                ldm_x4(bb[jn], stg + OFF_B + bOff + jn * (16 * PITCH) + ks * 32);
            // 16 MMAs, every accumulator touched exactly once per ks -> full ILP
            #pragma unroll
            for (int im = 0; im < 2; im++)
                #pragma unroll
                for (int jn = 0; jn < 4; jn++) {
                    mma4h(acc[im][2 * jn],     ah[im], bb[jn] + 0);
                    mma4h(acc[im][2 * jn + 1], ah[im], bb[jn] + 2);
                }
        }
        __syncthreads();
    }

    // ---- Epilogue ----
    const int r0 = bm + warp_m * 32 + (lane >> 2);
    const int c0 = bn + warp_n * 64 + (lane & 3) * 2;

    if (EPI == 0) {
        Cf += (size_t)z * cSlot;
        #pragma unroll
        for (int im = 0; im < 2; im++)
            #pragma unroll
            for (int j = 0; j < 8; j++) {
                const int row = r0 + im * 16;
                const int col = c0 + j * 8;
                const float s0 = rowScale ? rowScale[row] : alpha;
                const float s1 = rowScale ? rowScale[row + 8] : alpha;
                float2 v0 = make_float2(s0 * acc[im][j][0], s0 * acc[im][j][1]);
                float2 v1 = make_float2(s1 * acc[im][j][2], s1 * acc[im][j][3]);
                *reinterpret_cast<float2*>(&Cf[(size_t)row * N + col]) = v0;
                *reinterpret_cast<float2*>(&Cf[(size_t)(row + 8) * N + col]) = v1;
            }
    } else {
        const float* bias = (z == 0) ? bias0 : (z == 1) ? bias1 : bias2;
        Ch += (size_t)z * cSlot;
        #pragma unroll
        for (int im = 0; im < 2; im++)
            #pragma unroll
            for (int j = 0; j < 8; j++) {
                const int row = r0 + im * 16;
                const int col = c0 + j * 8;
                const float b0 = bias[col], b1 = bias[col + 1];
                #pragma unroll
                for (int h = 0; h < 2; h++) {
                    const int rw = row + h * 8;
                    __half2 hv;
                    hv.x = __float2half_rn(acc[im][j][h * 2 + 0] + b0);
                    hv.y = __float2half_rn(acc[im][j][h * 2 + 1] + b1);
                    *reinterpret_cast<__half2*>(&Ch[(size_t)rw * N + col]) = hv;
                }
            }
    }
}

// ---------------------------------------------------------------------------
// X fp32 -> fp16
// ---------------------------------------------------------------------------
__global__ __launch_bounds__(256) void xcast(
    const float* __restrict__ X, __half* __restrict__ Xh)
{
    const size_t i = ((size_t)blockIdx.x * 256 + threadIdx.x) * 4;
    float4 v = *reinterpret_cast<const float4*>(&X[i]);
    __half2 h0, h1;
    h0.x = __float2half_rn(v.x); h0.y = __float2half_rn(v.y);
    h1.x = __float2half_rn(v.z); h1.y = __float2half_rn(v.w);
    *reinterpret_cast<__half2*>(&Xh[i]) = h0;
    *reinterpret_cast<__half2*>(&Xh[i + 2]) = h1;
}

// ---------------------------------------------------------------------------
// W [K][N] fp32 -> W^T [n][k] fp16, slot z
// ---------------------------------------------------------------------------
__global__ void wtrans(const float* __restrict__ Wq, const float* __restrict__ Wk,
                       const float* __restrict__ Wv, __half* __restrict__ Th)
{
    __shared__ float tile[32][33];
    const int z = blockIdx.z;
    const float* W = (z == 0) ? Wq : (z == 1) ? Wk : Wv;
    const int n0 = blockIdx.x * 32, k0 = blockIdx.y * 32;
    const int tx = threadIdx.x, ty = threadIdx.y;
    #pragma unroll
    for (int i = 0; i < 32; i += 8)
        tile[ty + i][tx] = W[(size_t)(k0 + ty + i) * DIM + n0 + tx];
    __syncthreads();
    const size_t base = (size_t)z * DIM * DIM;
    #pragma unroll
    for (int i = 0; i < 32; i += 8)
        Th[base + (size_t)(n0 + ty + i) * DIM + k0 + tx] =
            __float2half_rn(tile[tx][ty + i]);
}

// ---------------------------------------------------------------------------
// V fp16 [SEQ][DIM] -> V^T fp16 [DIM][SEQ]
// ---------------------------------------------------------------------------
__global__ void vtrans(const __half* __restrict__ V, __half* __restrict__ Vt)
{
    __shared__ __half t[32][33];
    const int d0 = blockIdx.x * 32, s0 = blockIdx.y * 32;
    const int tx = threadIdx.x, ty = threadIdx.y;
    #pragma unroll
    for (int i = 0; i < 32; i += 8)
        t[ty + i][tx] = V[(size_t)(s0 + ty + i) * DIM + d0 + tx];
    __syncthreads();
    #pragma unroll
    for (int i = 0; i < 32; i += 8)
        Vt[(size_t)(d0 + ty + i) * SEQ + s0 + tx] = t[tx][ty + i];
}

// ---------------------------------------------------------------------------
// Row softmax (deferred normalization): Ph = fp16(exp(S - max)),
// rowinv = 1/rowsum (applied in PV epilogue). One block per row.
// ---------------------------------------------------------------------------
__global__ __launch_bounds__(256) void softmax_h(
    const float* __restrict__ S, __half* __restrict__ Ph,
    float* __restrict__ rowinv)
{
    const size_t rowoff = (size_t)blockIdx.x * SEQ;
    const float* p = S + rowoff;
    __shared__ float red[256];
    const int tid = threadIdx.x;

    float m = -INFINITY;
    #pragma unroll
    for (int t = 0; t < 4; t++) {
        float4 v = *reinterpret_cast<const float4*>(&p[tid * 4 + t * 1024]);
        m = fmaxf(m, fmaxf(fmaxf(v.x, v.y), fmaxf(v.z, v.w)));
    }
    red[tid] = m;
    __syncthreads();
    for (int s = 128; s > 0; s >>= 1) {
        if (tid < s) red[tid] = fmaxf(red[tid], red[tid + s]);
        __syncthreads();
    }
    m = red[0];
    __syncthreads();

    float sum = 0.0f;
    #pragma unroll
    for (int t = 0; t < 4; t++) {
        const int i = tid * 4 + t * 1024;
        float4 v = *reinterpret_cast<const float4*>(&p[i]);
        v.x = expf(v.x - m); v.y = expf(v.y - m);
        v.z = expf(v.z - m); v.w = expf(v.w - m);
        sum += v.x + v.y + v.z + v.w;
        __half2 h0, h1;
        h0.x = __float2half_rn(v.x); h0.y = __float2half_rn(v.y);
        h1.x = __float2half_rn(v.z); h1.y = __float2half_rn(v.w);
        *reinterpret_cast<__half2*>(&Ph[rowoff + i]) = h0;
        *reinterpret_cast<__half2*>(&Ph[rowoff + i + 2]) = h1;
    }
    red[tid] = sum;
    __syncthreads();
    for (int s = 128; s > 0; s >>= 1) {
        if (tid < s) red[tid] += red[tid + s];
        __syncthreads();
    }
    if (tid == 0) rowinv[blockIdx.x] = 1.0f / red[0];
}

// ---------------------------------------------------------------------------
// Launch — ordered so the ncu capture (launch #4) hits the big QK^T GEMM.
// ---------------------------------------------------------------------------
extern "C" void kernel_launch(void* const* d_in, const int* in_sizes, int n_in,
                              void* d_out, int out_size)
{
    const float* X  = (const float*)d_in[0];
    const float* Wq = (const float*)d_in[1];
    const float* bq = (const float*)d_in[2];
    const float* Wk = (const float*)d_in[3];
    const float* bk = (const float*)d_in[4];
    const float* Wv = (const float*)d_in[5];
    const float* bv = (const float*)d_in[6];
    float* out = (float*)d_out;

    __half *Xh, *Wth, *QKVh, *Vth, *Ph;
    float *S, *rowinv;
    cudaGetSymbolAddress((void**)&Xh, g_Xh);
    cudaGetSymbolAddress((void**)&Wth, g_Wth);
    cudaGetSymbolAddress((void**)&QKVh, g_QKVh);
    cudaGetSymbolAddress((void**)&Vth, g_Vth);
    cudaGetSymbolAddress((void**)&S, g_S);
    cudaGetSymbolAddress((void**)&Ph, g_Ph);
    cudaGetSymbolAddress((void**)&rowinv, g_rowinv);

    cudaFuncSetAttribute(h16_gemm<0>, cudaFuncAttributeMaxDynamicSharedMemorySize, SMEM_BYTES);
    cudaFuncSetAttribute(h16_gemm<1>, cudaFuncAttributeMaxDynamicSharedMemorySize, SMEM_BYTES);

    // 1) X -> fp16
    xcast<<<SEQ * DIM / 1024, 256>>>(X, Xh);
    // 2) W -> W^T fp16 (3 slots)
    wtrans<<<dim3(DIM / 32, DIM / 32, 3), dim3(32, 8)>>>(Wq, Wk, Wv, Wth);
    // 3) QKV projections (fused over z) + bias -> fp16
    h16_gemm<1><<<dim3(DIM / 128, SEQ / 128, 3), 256, SMEM_BYTES>>>(
        Xh, Wth, bq, bk, bv, nullptr,
        nullptr, QKVh,
        SEQ, DIM, DIM, 1.0f, (size_t)DIM * DIM, (size_t)SEQ * DIM);
    // 4) S = (Q @ K^T) / 32   <-- ncu capture target (launch #4)
    h16_gemm<0><<<dim3(SEQ / 128, SEQ / 128, 1), 256, SMEM_BYTES>>>(
        QKVh, QKVh + (size_t)SEQ * DIM,
        nullptr, nullptr, nullptr, nullptr,
        S, nullptr,
        SEQ, SEQ, DIM, 1.0f / 32.0f, 0, 0);
    // 5) V^T fp16
    vtrans<<<dim3(DIM / 32, SEQ / 32), dim3(32, 8)>>>(
        QKVh + 2 * (size_t)SEQ * DIM, Vth);
    // 6) softmax (deferred norm) -> P fp16 + rowinv
    softmax_h<<<SEQ, 256>>>(S, Ph, rowinv);
    // 7) out = (P @ V^T) * rowinv[row]
    h16_gemm<0><<<dim3(DIM / 128, SEQ / 128, 1), 256, SMEM_BYTES>>>(
        Ph, Vth,
        nullptr, nullptr, nullptr, rowinv,
        out, nullptr,
        SEQ, DIM, SEQ, 1.0f, 0, 0);
}